// round 12
// baseline (speedup 1.0000x reference)
#include <cuda_runtime.h>
#include <cuda_bf16.h>
#include <math.h>
#include <stdint.h>

#define B_  2
#define S_  2048
#define H_  2048
#define NH_ 16
#define HD_ 128

// int8 quantized operands (h = main, l = residual, x ~= s*(h + l/256))
__device__ int8_t g_h8h[(size_t)B_ * S_ * H_];
__device__ int8_t g_h8l[(size_t)B_ * S_ * H_];
__device__ int8_t g_wp8h[(size_t)3 * H_ * H_];
__device__ int8_t g_wp8l[(size_t)3 * H_ * H_];
__device__ int8_t g_wo8h[(size_t)H_ * H_];
__device__ int8_t g_wo8l[(size_t)H_ * H_];
__device__ int8_t g_ao8h[(size_t)B_ * S_ * H_];
__device__ int8_t g_ao8l[(size_t)B_ * S_ * H_];
__device__ float  g_sh[B_ * S_];
__device__ float  g_swp[3 * H_];
__device__ float  g_swo[H_];
__device__ float  g_sao[B_ * S_];

// bf16 hi/lo q/k/v for attention; fp32 attention output
__device__ __nv_bfloat16 g_q_hi[(size_t)B_ * NH_ * S_ * HD_];
__device__ __nv_bfloat16 g_q_lo[(size_t)B_ * NH_ * S_ * HD_];
__device__ __nv_bfloat16 g_k_hi[(size_t)B_ * NH_ * S_ * HD_];
__device__ __nv_bfloat16 g_k_lo[(size_t)B_ * NH_ * S_ * HD_];
__device__ __nv_bfloat16 g_v_hi[(size_t)B_ * NH_ * S_ * HD_];
__device__ __nv_bfloat16 g_v_lo[(size_t)B_ * NH_ * S_ * HD_];
__device__ float g_attn[(size_t)B_ * S_ * H_];

// ---------------------------------------------------------------------------
// helpers
// ---------------------------------------------------------------------------
__device__ __forceinline__ uint32_t smem_u32(const void* p) {
    uint32_t a;
    asm("{ .reg .u64 t; cvta.to.shared.u64 t, %1; cvt.u32.u64 %0, t; }" : "=r"(a) : "l"(p));
    return a;
}
#define LDSM_X4(r, addr) \
    asm volatile("ldmatrix.sync.aligned.m8n8.x4.shared.b16 {%0,%1,%2,%3}, [%4];" \
        : "=r"((r)[0]), "=r"((r)[1]), "=r"((r)[2]), "=r"((r)[3]) : "r"(addr))
#define LDSM_X4_T(r, addr) \
    asm volatile("ldmatrix.sync.aligned.m8n8.x4.trans.shared.b16 {%0,%1,%2,%3}, [%4];" \
        : "=r"((r)[0]), "=r"((r)[1]), "=r"((r)[2]), "=r"((r)[3]) : "r"(addr))

__device__ __forceinline__ void mma_bf16(float* c, const uint32_t* a, uint32_t b0, uint32_t b1) {
    asm volatile("mma.sync.aligned.m16n8k16.row.col.f32.bf16.bf16.f32 "
                 "{%0,%1,%2,%3}, {%4,%5,%6,%7}, {%8,%9}, {%0,%1,%2,%3};"
                 : "+f"(c[0]), "+f"(c[1]), "+f"(c[2]), "+f"(c[3])
                 : "r"(a[0]), "r"(a[1]), "r"(a[2]), "r"(a[3]), "r"(b0), "r"(b1));
}
__device__ __forceinline__ void mma_s8(int* c, const uint32_t* a, uint32_t b0, uint32_t b1) {
    asm volatile("mma.sync.aligned.m16n8k32.row.col.s32.s8.s8.s32 "
                 "{%0,%1,%2,%3}, {%4,%5,%6,%7}, {%8,%9}, {%0,%1,%2,%3};"
                 : "+r"(c[0]), "+r"(c[1]), "+r"(c[2]), "+r"(c[3])
                 : "r"(a[0]), "r"(a[1]), "r"(a[2]), "r"(a[3]), "r"(b0), "r"(b1));
}
__device__ __forceinline__ void cp16(uint32_t dst, const void* src) {
    asm volatile("cp.async.cg.shared.global [%0], [%1], 16;" :: "r"(dst), "l"(src) : "memory");
}
#define CP_COMMIT() asm volatile("cp.async.commit_group;" ::: "memory")
template <int N> __device__ __forceinline__ void cp_wait() {
    asm volatile("cp.async.wait_group %0;" :: "n"(N) : "memory");
}
__device__ __forceinline__ void pack_hilo(float x, float y, uint32_t& hi, uint32_t& lo) {
    __nv_bfloat162 h = __float22bfloat162_rn(make_float2(x, y));
    __nv_bfloat162 l = __float22bfloat162_rn(make_float2(x - __bfloat162float(h.x),
                                                         y - __bfloat162float(h.y)));
    hi = *reinterpret_cast<uint32_t*>(&h);
    lo = *reinterpret_cast<uint32_t*>(&l);
}
__device__ __forceinline__ int clamp127(int v) { return max(-127, min(127, v)); }
__device__ __forceinline__ uint32_t pk4(int a, int b, int c, int d) {
    return (uint32_t)(a & 255) | ((uint32_t)(b & 255) << 8) |
           ((uint32_t)(c & 255) << 16) | ((uint32_t)(d & 255) << 24);
}

// ---------------------------------------------------------------------------
// row quantization: fp32 row (K=2048) -> int8 h + int8 l + scale
// ---------------------------------------------------------------------------
__global__ __launch_bounds__(256)
void quant_rows(const float* __restrict__ src, int8_t* __restrict__ h8,
                int8_t* __restrict__ l8, float* __restrict__ scale)
{
    const int row = blockIdx.x;
    const float* p = src + (size_t)row * 2048;
    const int t = threadIdx.x, lane = t & 31, w = t >> 5;
    float x[8];
    *reinterpret_cast<float4*>(x)     = *reinterpret_cast<const float4*>(p + t * 8);
    *reinterpret_cast<float4*>(x + 4) = *reinterpret_cast<const float4*>(p + t * 8 + 4);
    float mx = 0.f;
    #pragma unroll
    for (int j = 0; j < 8; j++) mx = fmaxf(mx, fabsf(x[j]));
    #pragma unroll
    for (int off = 16; off; off >>= 1) mx = fmaxf(mx, __shfl_xor_sync(0xffffffffu, mx, off));
    __shared__ float wm[8];
    if (lane == 0) wm[w] = mx;
    __syncthreads();
    mx = wm[0];
    #pragma unroll
    for (int j = 1; j < 8; j++) mx = fmaxf(mx, wm[j]);

    const float s = mx * (1.f / 127.f);
    const float inv = (mx > 0.f) ? 127.f / mx : 0.f;
    const float inv2 = inv * 256.f;
    int h[8], l[8];
    #pragma unroll
    for (int j = 0; j < 8; j++) {
        h[j] = clamp127(__float2int_rn(x[j] * inv));
        const float r = x[j] - (float)h[j] * s;
        l[j] = clamp127(__float2int_rn(r * inv2));
    }
    *reinterpret_cast<uint2*>(h8 + (size_t)row * 2048 + t * 8) =
        make_uint2(pk4(h[0], h[1], h[2], h[3]), pk4(h[4], h[5], h[6], h[7]));
    *reinterpret_cast<uint2*>(l8 + (size_t)row * 2048 + t * 8) =
        make_uint2(pk4(l[0], l[1], l[2], l[3]), pk4(l[4], l[5], l[6], l[7]));
    if (t == 0) scale[row] = s;
}

// ---------------------------------------------------------------------------
// int8 3-term GEMM: C = A @ B^T, A,B int8 h/l + per-row scales.
// CTA 128x64, BK=64 int8, 256 threads, 2 CTA/SM, cp.async double buffer.
// EPI==0: emit q(scaled)/k/v bf16 hi/lo. EPI==1: fp32 store to C.
// ---------------------------------------------------------------------------
constexpr int AEL8 = 128 * 80;                  // bytes per A component
constexpr int BEL8 = 64 * 80;
constexpr int STG8 = 2 * AEL8 + 2 * BEL8;       // 30720
constexpr int GEMM_SMEM = 2 * STG8;             // 61440

template <int EPI>
__global__ __launch_bounds__(256, 2)
void gemm_s8(const int8_t* __restrict__ Ah, const int8_t* __restrict__ Al,
             const int8_t* __restrict__ Bh, const int8_t* __restrict__ Bl,
             const float* __restrict__ sa, const float* __restrict__ sb,
             float* __restrict__ C, int N, int K)
{
    extern __shared__ int8_t sm8[];
    const int bm = blockIdx.y * 128, bn = blockIdx.x * 64;
    const int tid = threadIdx.x, wid = tid >> 5, lane = tid & 31;
    const int wm = wid >> 1, wn = wid & 1;
    const int lrow = lane & 15;
    const int koff16 = (lane >> 4) * 16;
    const uint32_t smb = smem_u32(sm8);

    const int8_t* gA[2] = { Ah + (size_t)bm * K, Al + (size_t)bm * K };
    const int8_t* gB[2] = { Bh + (size_t)bn * K, Bl + (size_t)bn * K };

    auto load_stage = [&](int k0, int s) {
        const uint32_t sbb = smb + (uint32_t)(s * STG8);
        #pragma unroll
        for (int c = 0; c < 2; c++)
            #pragma unroll
            for (int i = 0; i < 2; i++) {
                const int idx = tid + i * 256;
                const int r = idx >> 2, q = idx & 3;
                cp16(sbb + (uint32_t)(c * AEL8 + r * 80 + q * 16),
                     gA[c] + (size_t)r * K + k0 + q * 16);
            }
        #pragma unroll
        for (int c = 0; c < 2; c++) {
            const int r = tid >> 2, q = tid & 3;
            cp16(sbb + (uint32_t)(2 * AEL8 + c * BEL8 + r * 80 + q * 16),
                 gB[c] + (size_t)r * K + k0 + q * 16);
        }
        CP_COMMIT();
    };

    int acc_h[2][4][4], acc_x[2][4][4];
    #pragma unroll
    for (int i = 0; i < 2; i++)
        #pragma unroll
        for (int j = 0; j < 4; j++)
            #pragma unroll
            for (int k = 0; k < 4; k++) { acc_h[i][j][k] = 0; acc_x[i][j][k] = 0; }

    const int niter = K >> 6;      // BK = 64
    load_stage(0, 0);

    for (int it = 0; it < niter; it++) {
        const int s = it & 1;
        if (it + 1 < niter) { load_stage((it + 1) << 6, s ^ 1); cp_wait<1>(); }
        else                { cp_wait<0>(); }
        __syncthreads();

        const uint32_t sbb = smb + (uint32_t)(s * STG8);
        #pragma unroll
        for (int kk = 0; kk < 2; kk++) {
            const uint32_t kb = (uint32_t)(kk * 32 + koff16);
            uint32_t bh4[2][4], bl4[2][4];
            #pragma unroll
            for (int nb = 0; nb < 2; nb++) {
                const uint32_t ok = sbb + (uint32_t)(2 * AEL8 + (wn * 32 + nb * 16 + lrow) * 80) + kb;
                LDSM_X4(bh4[nb], ok);
                LDSM_X4(bl4[nb], ok + (uint32_t)BEL8);
            }
            #pragma unroll
            for (int mi = 0; mi < 2; mi++) {
                uint32_t ah[4], al[4];
                const uint32_t oa = sbb + (uint32_t)((wm * 32 + mi * 16 + lrow) * 80) + kb;
                LDSM_X4(ah, oa);
                LDSM_X4(al, oa + (uint32_t)AEL8);
                #pragma unroll
                for (int nb = 0; nb < 2; nb++)
                    #pragma unroll
                    for (int hf = 0; hf < 2; hf++) {
                        const int nj = nb * 2 + hf;
                        mma_s8(acc_h[mi][nj], ah, bh4[nb][hf], bh4[nb][hf + 2]);
                        mma_s8(acc_x[mi][nj], ah, bl4[nb][hf], bl4[nb][hf + 2]);
                        mma_s8(acc_x[mi][nj], al, bh4[nb][hf], bh4[nb][hf + 2]);
                    }
            }
        }
        __syncthreads();
    }

    // epilogue: dequant C = sa[m]*sb[n]*(hh + cross/256)
    const int g = lane >> 2, t4 = lane & 3;
    #pragma unroll
    for (int mi = 0; mi < 2; mi++) {
        const int m0 = bm + wm * 32 + mi * 16 + g;
        const int m1 = m0 + 8;
        const float sa0 = sa[m0], sa1 = sa[m1];
        #pragma unroll
        for (int nj = 0; nj < 4; nj++) {
            const int col = wn * 32 + nj * 8 + 2 * t4;
            const float2 sbv = *reinterpret_cast<const float2*>(sb + bn + col);
            float f[4];
            f[0] = ((float)acc_h[mi][nj][0] + (float)acc_x[mi][nj][0] * 0.00390625f) * sa0 * sbv.x;
            f[1] = ((float)acc_h[mi][nj][1] + (float)acc_x[mi][nj][1] * 0.00390625f) * sa0 * sbv.y;
            f[2] = ((float)acc_h[mi][nj][2] + (float)acc_x[mi][nj][2] * 0.00390625f) * sa1 * sbv.x;
            f[3] = ((float)acc_h[mi][nj][3] + (float)acc_x[mi][nj][3] * 0.00390625f) * sa1 * sbv.y;
            if (EPI == 0) {
                const int gcol = bn + col;
                const int three = gcol >> 11;
                const int nh    = (gcol & 2047) >> 7;
                const int hd    = gcol & 127;
                __nv_bfloat16 *dh, *dl;
                if (three == 0)      { dh = g_q_hi; dl = g_q_lo; }
                else if (three == 1) { dh = g_k_hi; dl = g_k_lo; }
                else                 { dh = g_v_hi; dl = g_v_lo; }
                const float scl = (three == 0) ? 0.08838834764831845f : 1.0f;
                #pragma unroll
                for (int half = 0; half < 2; half++) {
                    const int m = (half == 0) ? m0 : m1;
                    const int bi = m >> 11, si = m & 2047;
                    const size_t o = (((size_t)bi * NH_ + nh) * S_ + si) * HD_ + hd;
                    uint32_t hv, lv;
                    pack_hilo(f[half * 2] * scl, f[half * 2 + 1] * scl, hv, lv);
                    *reinterpret_cast<uint32_t*>(dh + o) = hv;
                    *reinterpret_cast<uint32_t*>(dl + o) = lv;
                }
            } else {
                *reinterpret_cast<float2*>(C + (size_t)m0 * N + bn + col) = make_float2(f[0], f[1]);
                *reinterpret_cast<float2*>(C + (size_t)m1 * N + bn + col) = make_float2(f[2], f[3]);
            }
        }
    }
}

// ---------------------------------------------------------------------------
// Causal flash attention via bf16 mma.sync 3-term. BQ=128, BC=64, 256 threads.
// Output: fp32 g_attn [b, s, H].
// ---------------------------------------------------------------------------
constexpr int LDA_ = 136;
constexpr int QEL = 128 * LDA_;
constexpr int KEL = 64 * LDA_;
constexpr int OFF_K0 = 2 * QEL;
constexpr int OFF_V0 = 2 * QEL + 4 * KEL;
constexpr int ATTN_SMEM = (2 * QEL + 8 * KEL) * 2;   // 208896 B

__global__ __launch_bounds__(256)
void attn_mma()
{
    extern __shared__ __nv_bfloat16 sm[];
    const int q0 = blockIdx.x * 128;
    const int h = blockIdx.y, b = blockIdx.z;
    const int tid = threadIdx.x, wid = tid >> 5, lane = tid & 31;
    const int g = lane >> 2, t4 = lane & 3;
    const int lrow = lane & 15, lcol8 = (lane >> 4) * 8;
    const uint32_t smb = smem_u32(sm);

    const size_t hoff = ((size_t)b * NH_ + h) * S_ * HD_;
    const __nv_bfloat16* qh = g_q_hi + hoff + (size_t)q0 * HD_;
    const __nv_bfloat16* ql = g_q_lo + hoff + (size_t)q0 * HD_;
    const __nv_bfloat16* kh = g_k_hi + hoff;
    const __nv_bfloat16* kl = g_k_lo + hoff;
    const __nv_bfloat16* vhp = g_v_hi + hoff;
    const __nv_bfloat16* vlp = g_v_lo + hoff;

    #pragma unroll
    for (int i = 0; i < 8; i++) {
        const int idx = tid + i * 256;
        const int r = idx >> 4, q = idx & 15;
        *reinterpret_cast<uint4*>(sm + r * LDA_ + q * 8) =
            *reinterpret_cast<const uint4*>(qh + (size_t)r * HD_ + q * 8);
        *reinterpret_cast<uint4*>(sm + QEL + r * LDA_ + q * 8) =
            *reinterpret_cast<const uint4*>(ql + (size_t)r * HD_ + q * 8);
    }

    auto load_kv = [&](int t, int s) {
        const int j0 = t * 64;
        const uint32_t sk = smb + (uint32_t)(OFF_K0 + s * 2 * KEL) * 2;
        const uint32_t sv = smb + (uint32_t)(OFF_V0 + s * 2 * KEL) * 2;
        #pragma unroll
        for (int i = 0; i < 4; i++) {
            const int idx = tid + i * 256;
            const int r = idx >> 4, q = idx & 15;
            const uint32_t so = (uint32_t)(r * LDA_ + q * 8) * 2;
            const size_t go = (size_t)(j0 + r) * HD_ + q * 8;
            cp16(sk + so,                      kh + go);
            cp16(sk + (uint32_t)KEL * 2 + so,  kl + go);
            cp16(sv + so,                      vhp + go);
            cp16(sv + (uint32_t)KEL * 2 + so,  vlp + go);
        }
        CP_COMMIT();
    };

    const int ntiles = q0 / 64 + 2;
    load_kv(0, 0);

    float m0 = -1e30f, m1 = -1e30f, l0 = 0.f, l1 = 0.f;
    float oa[16][4];
    #pragma unroll
    for (int f = 0; f < 16; f++)
        #pragma unroll
        for (int k = 0; k < 4; k++) oa[f][k] = 0.f;

    const int rg0 = q0 + wid * 16 + g;
    const int rg1 = rg0 + 8;

    for (int t = 0; t < ntiles; t++) {
        const int st = t & 1;
        if (t + 1 < ntiles) { load_kv(t + 1, st ^ 1); cp_wait<1>(); }
        else                { cp_wait<0>(); }
        __syncthreads();

        const uint32_t sk = smb + (uint32_t)(OFF_K0 + st * 2 * KEL) * 2;
        const uint32_t sv = smb + (uint32_t)(OFF_V0 + st * 2 * KEL) * 2;

        float sc[8][4];
        #pragma unroll
        for (int nj = 0; nj < 8; nj++)
            #pragma unroll
            for (int k = 0; k < 4; k++) sc[nj][k] = 0.f;

        #pragma unroll
        for (int kc = 0; kc < 8; kc++) {
            uint32_t ah[4], al[4];
            const uint32_t oq = smb + (uint32_t)((wid * 16 + lrow) * LDA_ + kc * 16 + lcol8) * 2;
            LDSM_X4(ah, oq);
            LDSM_X4(al, oq + (uint32_t)QEL * 2);
            #pragma unroll
            for (int nb = 0; nb < 4; nb++) {
                uint32_t bh4[4], bl4[4];
                const uint32_t ok = sk + (uint32_t)((nb * 16 + lrow) * LDA_ + kc * 16 + lcol8) * 2;
                LDSM_X4(bh4, ok);
                LDSM_X4(bl4, ok + (uint32_t)KEL * 2);
                #pragma unroll
                for (int hf = 0; hf < 2; hf++) {
                    const int nj = nb * 2 + hf;
                    mma_bf16(sc[nj], ah, bh4[hf], bh4[hf + 2]);
                    mma_bf16(sc[nj], ah, bl4[hf], bl4[hf + 2]);
                    mma_bf16(sc[nj], al, bh4[hf], bh4[hf + 2]);
                }
            }
        }

        const int j0 = t * 64;
        if (t >= ntiles - 2) {
            #pragma unroll
            for (int nj = 0; nj < 8; nj++) {
                const int c0 = j0 + nj * 8 + 2 * t4;
                if (c0     > rg0) sc[nj][0] = -1e30f;
                if (c0 + 1 > rg0) sc[nj][1] = -1e30f;
                if (c0     > rg1) sc[nj][2] = -1e30f;
                if (c0 + 1 > rg1) sc[nj][3] = -1e30f;
            }
        }

        float mx0 = -1e30f, mx1 = -1e30f;
        #pragma unroll
        for (int nj = 0; nj < 8; nj++) {
            mx0 = fmaxf(mx0, fmaxf(sc[nj][0], sc[nj][1]));
            mx1 = fmaxf(mx1, fmaxf(sc[nj][2], sc[nj][3]));
        }
        mx0 = fmaxf(mx0, __shfl_xor_sync(0xffffffffu, mx0, 1));
        mx0 = fmaxf(mx0, __shfl_xor_sync(0xffffffffu, mx0, 2));
        mx1 = fmaxf(mx1, __shfl_xor_sync(0xffffffffu, mx1, 1));
        mx1 = fmaxf(mx1, __shfl_xor_sync(0xffffffffu, mx1, 2));
        const float mn0 = fmaxf(m0, mx0), mn1 = fmaxf(m1, mx1);
        const float cr0 = __expf(m0 - mn0), cr1 = __expf(m1 - mn1);
        m0 = mn0; m1 = mn1;
        float rs0 = 0.f, rs1 = 0.f;
        #pragma unroll
        for (int nj = 0; nj < 8; nj++) {
            sc[nj][0] = __expf(sc[nj][0] - mn0);
            sc[nj][1] = __expf(sc[nj][1] - mn0);
            sc[nj][2] = __expf(sc[nj][2] - mn1);
            sc[nj][3] = __expf(sc[nj][3] - mn1);
            rs0 += sc[nj][0] + sc[nj][1];
            rs1 += sc[nj][2] + sc[nj][3];
        }
        rs0 += __shfl_xor_sync(0xffffffffu, rs0, 1);
        rs0 += __shfl_xor_sync(0xffffffffu, rs0, 2);
        rs1 += __shfl_xor_sync(0xffffffffu, rs1, 1);
        rs1 += __shfl_xor_sync(0xffffffffu, rs1, 2);
        l0 = l0 * cr0 + rs0;
        l1 = l1 * cr1 + rs1;
        #pragma unroll
        for (int f = 0; f < 16; f++) {
            oa[f][0] *= cr0; oa[f][1] *= cr0;
            oa[f][2] *= cr1; oa[f][3] *= cr1;
        }

        #pragma unroll
        for (int kc = 0; kc < 4; kc++) {
            uint32_t ph[4], pl[4];
            pack_hilo(sc[2 * kc][0],     sc[2 * kc][1],     ph[0], pl[0]);
            pack_hilo(sc[2 * kc][2],     sc[2 * kc][3],     ph[1], pl[1]);
            pack_hilo(sc[2 * kc + 1][0], sc[2 * kc + 1][1], ph[2], pl[2]);
            pack_hilo(sc[2 * kc + 1][2], sc[2 * kc + 1][3], ph[3], pl[3]);
            #pragma unroll
            for (int dn = 0; dn < 8; dn++) {
                uint32_t vh4[4], vl4[4];
                const uint32_t ov = sv + (uint32_t)((kc * 16 + lrow) * LDA_ + dn * 16 + lcol8) * 2;
                LDSM_X4_T(vh4, ov);
                LDSM_X4_T(vl4, ov + (uint32_t)KEL * 2);
                mma_bf16(oa[2 * dn],     ph, vh4[0], vh4[1]);
                mma_bf16(oa[2 * dn],     ph, vl4[0], vl4[1]);
                mma_bf16(oa[2 * dn],     pl, vh4[0], vh4[1]);
                mma_bf16(oa[2 * dn + 1], ph, vh4[2], vh4[3]);
                mma_bf16(oa[2 * dn + 1], ph, vl4[2], vl4[3]);
                mma_bf16(oa[2 * dn + 1], pl, vh4[2], vh4[3]);
            }
        }
        __syncthreads();
    }

    const float i0 = 1.f / l0, i1 = 1.f / l1;
    const int r0 = q0 + wid * 16 + g;
    #pragma unroll
    for (int f = 0; f < 16; f++) {
        const int col = f * 8 + 2 * t4;
        const size_t o0 = ((size_t)b * S_ + r0) * H_ + h * HD_ + col;
        const size_t o1 = ((size_t)b * S_ + r0 + 8) * H_ + h * HD_ + col;
        *reinterpret_cast<float2*>(g_attn + o0) = make_float2(oa[f][0] * i0, oa[f][1] * i0);
        *reinterpret_cast<float2*>(g_attn + o1) = make_float2(oa[f][2] * i1, oa[f][3] * i1);
    }
}

// ---------------------------------------------------------------------------
extern "C" void kernel_launch(void* const* d_in, const int* in_sizes, int n_in,
                              void* d_out, int out_size)
{
    (void)in_sizes; (void)n_in; (void)out_size;
    const float* hidden = (const float*)d_in[0];
    // d_in[1] = attention_mask: deterministic causal mask, implemented directly.
    const float* w_pack = (const float*)d_in[2];
    const float* w_o    = (const float*)d_in[3];
    float* out = (float*)d_out;

    cudaFuncSetAttribute(gemm_s8<0>, cudaFuncAttributeMaxDynamicSharedMemorySize, GEMM_SMEM);
    cudaFuncSetAttribute(gemm_s8<1>, cudaFuncAttributeMaxDynamicSharedMemorySize, GEMM_SMEM);
    cudaFuncSetAttribute(attn_mma, cudaFuncAttributeMaxDynamicSharedMemorySize, ATTN_SMEM);

    int8_t *h8h, *h8l, *wp8h, *wp8l, *wo8h, *wo8l, *ao8h, *ao8l;
    float *sh, *swp, *swo, *sao, *attn_ptr;
    cudaGetSymbolAddress((void**)&h8h,  g_h8h);  cudaGetSymbolAddress((void**)&h8l,  g_h8l);
    cudaGetSymbolAddress((void**)&wp8h, g_wp8h); cudaGetSymbolAddress((void**)&wp8l, g_wp8l);
    cudaGetSymbolAddress((void**)&wo8h, g_wo8h); cudaGetSymbolAddress((void**)&wo8l, g_wo8l);
    cudaGetSymbolAddress((void**)&ao8h, g_ao8h); cudaGetSymbolAddress((void**)&ao8l, g_ao8l);
    cudaGetSymbolAddress((void**)&sh,  g_sh);  cudaGetSymbolAddress((void**)&swp, g_swp);
    cudaGetSymbolAddress((void**)&swo, g_swo); cudaGetSymbolAddress((void**)&sao, g_sao);
    cudaGetSymbolAddress((void**)&attn_ptr, g_attn);

    const int M = B_ * S_;                       // 4096

    // quantize inputs (per row over K=2048)
    quant_rows<<<M, 256>>>(hidden, h8h, h8l, sh);
    quant_rows<<<3 * H_, 256>>>(w_pack, wp8h, wp8l, swp);
    quant_rows<<<H_, 256>>>(w_o, wo8h, wo8l, swo);

    // K1: QKV projection (int8 3-term) -> q/k/v bf16 hi/lo (q pre-scaled)
    dim3 g1((3 * H_) / 64, M / 128);             // (96, 32)
    gemm_s8<0><<<g1, 256, GEMM_SMEM>>>(h8h, h8l, wp8h, wp8l, sh, swp, nullptr, 3 * H_, H_);

    // K2: causal flash attention (bf16 mma 3-term) -> g_attn fp32
    dim3 g2(S_ / 128, NH_, B_);                  // (16, 16, 2)
    attn_mma<<<g2, 256, ATTN_SMEM>>>();

    // quantize attention output
    quant_rows<<<M, 256>>>(attn_ptr, ao8h, ao8l, sao);

    // K3: output projection (int8 3-term) -> d_out (fp32)
    dim3 g3(H_ / 64, M / 128);                   // (32, 32)
    gemm_s8<1><<<g3, 256, GEMM_SMEM>>>(ao8h, ao8l, wo8h, wo8l, sao, swo, out, H_, H_);
}

// round 13
// speedup vs baseline: 1.0004x; 1.0004x over previous
#include <cuda_runtime.h>
#include <cuda_bf16.h>
#include <math.h>
#include <stdint.h>

#define B_  2
#define S_  2048
#define H_  2048
#define NH_ 16
#define HD_ 128

// int8 quantized operands (h = main, l = residual, x ~= s*(h + l/256))
__device__ int8_t g_h8h[(size_t)B_ * S_ * H_];
__device__ int8_t g_h8l[(size_t)B_ * S_ * H_];
__device__ int8_t g_wp8h[(size_t)3 * H_ * H_];
__device__ int8_t g_wp8l[(size_t)3 * H_ * H_];
__device__ int8_t g_wo8h[(size_t)H_ * H_];
__device__ int8_t g_wo8l[(size_t)H_ * H_];
__device__ int8_t g_ao8h[(size_t)B_ * S_ * H_];
__device__ int8_t g_ao8l[(size_t)B_ * S_ * H_];
__device__ float  g_sh[B_ * S_];
__device__ float  g_swp[3 * H_];
__device__ float  g_swo[H_];
__device__ float  g_sao[B_ * S_];

// bf16 hi/lo q/k/v for attention; fp32 attention output
__device__ __nv_bfloat16 g_q_hi[(size_t)B_ * NH_ * S_ * HD_];
__device__ __nv_bfloat16 g_q_lo[(size_t)B_ * NH_ * S_ * HD_];
__device__ __nv_bfloat16 g_k_hi[(size_t)B_ * NH_ * S_ * HD_];
__device__ __nv_bfloat16 g_k_lo[(size_t)B_ * NH_ * S_ * HD_];
__device__ __nv_bfloat16 g_v_hi[(size_t)B_ * NH_ * S_ * HD_];
__device__ __nv_bfloat16 g_v_lo[(size_t)B_ * NH_ * S_ * HD_];
__device__ float g_attn[(size_t)B_ * S_ * H_];

// ---------------------------------------------------------------------------
// helpers
// ---------------------------------------------------------------------------
__device__ __forceinline__ uint32_t smem_u32(const void* p) {
    uint32_t a;
    asm("{ .reg .u64 t; cvta.to.shared.u64 t, %1; cvt.u32.u64 %0, t; }" : "=r"(a) : "l"(p));
    return a;
}
#define LDSM_X4(r, addr) \
    asm volatile("ldmatrix.sync.aligned.m8n8.x4.shared.b16 {%0,%1,%2,%3}, [%4];" \
        : "=r"((r)[0]), "=r"((r)[1]), "=r"((r)[2]), "=r"((r)[3]) : "r"(addr))
#define LDSM_X4_T(r, addr) \
    asm volatile("ldmatrix.sync.aligned.m8n8.x4.trans.shared.b16 {%0,%1,%2,%3}, [%4];" \
        : "=r"((r)[0]), "=r"((r)[1]), "=r"((r)[2]), "=r"((r)[3]) : "r"(addr))

__device__ __forceinline__ void mma_bf16(float* c, const uint32_t* a, uint32_t b0, uint32_t b1) {
    asm volatile("mma.sync.aligned.m16n8k16.row.col.f32.bf16.bf16.f32 "
                 "{%0,%1,%2,%3}, {%4,%5,%6,%7}, {%8,%9}, {%0,%1,%2,%3};"
                 : "+f"(c[0]), "+f"(c[1]), "+f"(c[2]), "+f"(c[3])
                 : "r"(a[0]), "r"(a[1]), "r"(a[2]), "r"(a[3]), "r"(b0), "r"(b1));
}
__device__ __forceinline__ void mma_s8(int* c, const uint32_t* a, uint32_t b0, uint32_t b1) {
    asm volatile("mma.sync.aligned.m16n8k32.row.col.s32.s8.s8.s32 "
                 "{%0,%1,%2,%3}, {%4,%5,%6,%7}, {%8,%9}, {%0,%1,%2,%3};"
                 : "+r"(c[0]), "+r"(c[1]), "+r"(c[2]), "+r"(c[3])
                 : "r"(a[0]), "r"(a[1]), "r"(a[2]), "r"(a[3]), "r"(b0), "r"(b1));
}
__device__ __forceinline__ void cp16(uint32_t dst, const void* src) {
    asm volatile("cp.async.cg.shared.global [%0], [%1], 16;" :: "r"(dst), "l"(src) : "memory");
}
#define CP_COMMIT() asm volatile("cp.async.commit_group;" ::: "memory")
template <int N> __device__ __forceinline__ void cp_wait() {
    asm volatile("cp.async.wait_group %0;" :: "n"(N) : "memory");
}
__device__ __forceinline__ void pack_hilo(float x, float y, uint32_t& hi, uint32_t& lo) {
    __nv_bfloat162 h = __float22bfloat162_rn(make_float2(x, y));
    __nv_bfloat162 l = __float22bfloat162_rn(make_float2(x - __bfloat162float(h.x),
                                                         y - __bfloat162float(h.y)));
    hi = *reinterpret_cast<uint32_t*>(&h);
    lo = *reinterpret_cast<uint32_t*>(&l);
}
__device__ __forceinline__ int clamp127(int v) { return max(-127, min(127, v)); }
__device__ __forceinline__ uint32_t pk4(int a, int b, int c, int d) {
    return (uint32_t)(a & 255) | ((uint32_t)(b & 255) << 8) |
           ((uint32_t)(c & 255) << 16) | ((uint32_t)(d & 255) << 24);
}

// ---------------------------------------------------------------------------
// row quantization: fp32 row (K=2048) -> int8 h + int8 l + scale
// ---------------------------------------------------------------------------
__global__ __launch_bounds__(256)
void quant_rows(const float* __restrict__ src, int8_t* __restrict__ h8,
                int8_t* __restrict__ l8, float* __restrict__ scale)
{
    const int row = blockIdx.x;
    const float* p = src + (size_t)row * 2048;
    const int t = threadIdx.x, lane = t & 31, w = t >> 5;
    float x[8];
    *reinterpret_cast<float4*>(x)     = *reinterpret_cast<const float4*>(p + t * 8);
    *reinterpret_cast<float4*>(x + 4) = *reinterpret_cast<const float4*>(p + t * 8 + 4);
    float mx = 0.f;
    #pragma unroll
    for (int j = 0; j < 8; j++) mx = fmaxf(mx, fabsf(x[j]));
    #pragma unroll
    for (int off = 16; off; off >>= 1) mx = fmaxf(mx, __shfl_xor_sync(0xffffffffu, mx, off));
    __shared__ float wm[8];
    if (lane == 0) wm[w] = mx;
    __syncthreads();
    mx = wm[0];
    #pragma unroll
    for (int j = 1; j < 8; j++) mx = fmaxf(mx, wm[j]);

    const float s = mx * (1.f / 127.f);
    const float inv = (mx > 0.f) ? 127.f / mx : 0.f;
    const float inv2 = inv * 256.f;
    int h[8], l[8];
    #pragma unroll
    for (int j = 0; j < 8; j++) {
        h[j] = clamp127(__float2int_rn(x[j] * inv));
        const float r = x[j] - (float)h[j] * s;
        l[j] = clamp127(__float2int_rn(r * inv2));
    }
    *reinterpret_cast<uint2*>(h8 + (size_t)row * 2048 + t * 8) =
        make_uint2(pk4(h[0], h[1], h[2], h[3]), pk4(h[4], h[5], h[6], h[7]));
    *reinterpret_cast<uint2*>(l8 + (size_t)row * 2048 + t * 8) =
        make_uint2(pk4(l[0], l[1], l[2], l[3]), pk4(l[4], l[5], l[6], l[7]));
    if (t == 0) scale[row] = s;
}

// ---------------------------------------------------------------------------
// int8 3-term GEMM: C = A @ B^T, A,B int8 h/l + per-row scales.
// CTA 128x64, BK=64 int8, 256 threads, 2 CTA/SM, cp.async double buffer.
// EPI==0: emit q(scaled)/k/v bf16 hi/lo. EPI==1: fp32 store to C.
// ---------------------------------------------------------------------------
constexpr int AEL8 = 128 * 80;                  // bytes per A component
constexpr int BEL8 = 64 * 80;
constexpr int STG8 = 2 * AEL8 + 2 * BEL8;       // 30720
constexpr int GEMM_SMEM = 2 * STG8;             // 61440

template <int EPI>
__global__ __launch_bounds__(256, 2)
void gemm_s8(const int8_t* __restrict__ Ah, const int8_t* __restrict__ Al,
             const int8_t* __restrict__ Bh, const int8_t* __restrict__ Bl,
             const float* __restrict__ sa, const float* __restrict__ sb,
             float* __restrict__ C, int N, int K)
{
    extern __shared__ int8_t sm8[];
    const int bm = blockIdx.y * 128, bn = blockIdx.x * 64;
    const int tid = threadIdx.x, wid = tid >> 5, lane = tid & 31;
    const int wm = wid >> 1, wn = wid & 1;
    const int lrow = lane & 15;
    const int koff16 = (lane >> 4) * 16;
    const uint32_t smb = smem_u32(sm8);

    const int8_t* gA[2] = { Ah + (size_t)bm * K, Al + (size_t)bm * K };
    const int8_t* gB[2] = { Bh + (size_t)bn * K, Bl + (size_t)bn * K };

    auto load_stage = [&](int k0, int s) {
        const uint32_t sbb = smb + (uint32_t)(s * STG8);
        #pragma unroll
        for (int c = 0; c < 2; c++)
            #pragma unroll
            for (int i = 0; i < 2; i++) {
                const int idx = tid + i * 256;
                const int r = idx >> 2, q = idx & 3;
                cp16(sbb + (uint32_t)(c * AEL8 + r * 80 + q * 16),
                     gA[c] + (size_t)r * K + k0 + q * 16);
            }
        #pragma unroll
        for (int c = 0; c < 2; c++) {
            const int r = tid >> 2, q = tid & 3;
            cp16(sbb + (uint32_t)(2 * AEL8 + c * BEL8 + r * 80 + q * 16),
                 gB[c] + (size_t)r * K + k0 + q * 16);
        }
        CP_COMMIT();
    };

    int acc_h[2][4][4], acc_x[2][4][4];
    #pragma unroll
    for (int i = 0; i < 2; i++)
        #pragma unroll
        for (int j = 0; j < 4; j++)
            #pragma unroll
            for (int k = 0; k < 4; k++) { acc_h[i][j][k] = 0; acc_x[i][j][k] = 0; }

    const int niter = K >> 6;      // BK = 64
    load_stage(0, 0);

    for (int it = 0; it < niter; it++) {
        const int s = it & 1;
        if (it + 1 < niter) { load_stage((it + 1) << 6, s ^ 1); cp_wait<1>(); }
        else                { cp_wait<0>(); }
        __syncthreads();

        const uint32_t sbb = smb + (uint32_t)(s * STG8);
        #pragma unroll
        for (int kk = 0; kk < 2; kk++) {
            const uint32_t kb = (uint32_t)(kk * 32 + koff16);
            uint32_t bh4[2][4], bl4[2][4];
            #pragma unroll
            for (int nb = 0; nb < 2; nb++) {
                const uint32_t ok = sbb + (uint32_t)(2 * AEL8 + (wn * 32 + nb * 16 + lrow) * 80) + kb;
                LDSM_X4(bh4[nb], ok);
                LDSM_X4(bl4[nb], ok + (uint32_t)BEL8);
            }
            #pragma unroll
            for (int mi = 0; mi < 2; mi++) {
                uint32_t ah[4], al[4];
                const uint32_t oa = sbb + (uint32_t)((wm * 32 + mi * 16 + lrow) * 80) + kb;
                LDSM_X4(ah, oa);
                LDSM_X4(al, oa + (uint32_t)AEL8);
                #pragma unroll
                for (int nb = 0; nb < 2; nb++)
                    #pragma unroll
                    for (int hf = 0; hf < 2; hf++) {
                        const int nj = nb * 2 + hf;
                        mma_s8(acc_h[mi][nj], ah, bh4[nb][hf], bh4[nb][hf + 2]);
                        mma_s8(acc_x[mi][nj], ah, bl4[nb][hf], bl4[nb][hf + 2]);
                        mma_s8(acc_x[mi][nj], al, bh4[nb][hf], bh4[nb][hf + 2]);
                    }
            }
        }
        __syncthreads();
    }

    // epilogue: dequant C = sa[m]*sb[n]*(hh + cross/256)
    const int g = lane >> 2, t4 = lane & 3;
    #pragma unroll
    for (int mi = 0; mi < 2; mi++) {
        const int m0 = bm + wm * 32 + mi * 16 + g;
        const int m1 = m0 + 8;
        const float sa0 = sa[m0], sa1 = sa[m1];
        #pragma unroll
        for (int nj = 0; nj < 4; nj++) {
            const int col = wn * 32 + nj * 8 + 2 * t4;
            const float2 sbv = *reinterpret_cast<const float2*>(sb + bn + col);
            float f[4];
            f[0] = ((float)acc_h[mi][nj][0] + (float)acc_x[mi][nj][0] * 0.00390625f) * sa0 * sbv.x;
            f[1] = ((float)acc_h[mi][nj][1] + (float)acc_x[mi][nj][1] * 0.00390625f) * sa0 * sbv.y;
            f[2] = ((float)acc_h[mi][nj][2] + (float)acc_x[mi][nj][2] * 0.00390625f) * sa1 * sbv.x;
            f[3] = ((float)acc_h[mi][nj][3] + (float)acc_x[mi][nj][3] * 0.00390625f) * sa1 * sbv.y;
            if (EPI == 0) {
                const int gcol = bn + col;
                const int three = gcol >> 11;
                const int nh    = (gcol & 2047) >> 7;
                const int hd    = gcol & 127;
                __nv_bfloat16 *dh, *dl;
                if (three == 0)      { dh = g_q_hi; dl = g_q_lo; }
                else if (three == 1) { dh = g_k_hi; dl = g_k_lo; }
                else                 { dh = g_v_hi; dl = g_v_lo; }
                const float scl = (three == 0) ? 0.08838834764831845f : 1.0f;
                #pragma unroll
                for (int half = 0; half < 2; half++) {
                    const int m = (half == 0) ? m0 : m1;
                    const int bi = m >> 11, si = m & 2047;
                    const size_t o = (((size_t)bi * NH_ + nh) * S_ + si) * HD_ + hd;
                    uint32_t hv, lv;
                    pack_hilo(f[half * 2] * scl, f[half * 2 + 1] * scl, hv, lv);
                    *reinterpret_cast<uint32_t*>(dh + o) = hv;
                    *reinterpret_cast<uint32_t*>(dl + o) = lv;
                }
            } else {
                *reinterpret_cast<float2*>(C + (size_t)m0 * N + bn + col) = make_float2(f[0], f[1]);
                *reinterpret_cast<float2*>(C + (size_t)m1 * N + bn + col) = make_float2(f[2], f[3]);
            }
        }
    }
}

// ---------------------------------------------------------------------------
// Causal flash attention via bf16 mma.sync 3-term. BQ=128, BC=64, 256 threads.
// Output: fp32 g_attn [b, s, H].
// ---------------------------------------------------------------------------
constexpr int LDA_ = 136;
constexpr int QEL = 128 * LDA_;
constexpr int KEL = 64 * LDA_;
constexpr int OFF_K0 = 2 * QEL;
constexpr int OFF_V0 = 2 * QEL + 4 * KEL;
constexpr int ATTN_SMEM = (2 * QEL + 8 * KEL) * 2;   // 208896 B

__global__ __launch_bounds__(256)
void attn_mma()
{
    extern __shared__ __nv_bfloat16 sm[];
    const int q0 = blockIdx.x * 128;
    const int h = blockIdx.y, b = blockIdx.z;
    const int tid = threadIdx.x, wid = tid >> 5, lane = tid & 31;
    const int g = lane >> 2, t4 = lane & 3;
    const int lrow = lane & 15, lcol8 = (lane >> 4) * 8;
    const uint32_t smb = smem_u32(sm);

    const size_t hoff = ((size_t)b * NH_ + h) * S_ * HD_;
    const __nv_bfloat16* qh = g_q_hi + hoff + (size_t)q0 * HD_;
    const __nv_bfloat16* ql = g_q_lo + hoff + (size_t)q0 * HD_;
    const __nv_bfloat16* kh = g_k_hi + hoff;
    const __nv_bfloat16* kl = g_k_lo + hoff;
    const __nv_bfloat16* vhp = g_v_hi + hoff;
    const __nv_bfloat16* vlp = g_v_lo + hoff;

    #pragma unroll
    for (int i = 0; i < 8; i++) {
        const int idx = tid + i * 256;
        const int r = idx >> 4, q = idx & 15;
        *reinterpret_cast<uint4*>(sm + r * LDA_ + q * 8) =
            *reinterpret_cast<const uint4*>(qh + (size_t)r * HD_ + q * 8);
        *reinterpret_cast<uint4*>(sm + QEL + r * LDA_ + q * 8) =
            *reinterpret_cast<const uint4*>(ql + (size_t)r * HD_ + q * 8);
    }

    auto load_kv = [&](int t, int s) {
        const int j0 = t * 64;
        const uint32_t sk = smb + (uint32_t)(OFF_K0 + s * 2 * KEL) * 2;
        const uint32_t sv = smb + (uint32_t)(OFF_V0 + s * 2 * KEL) * 2;
        #pragma unroll
        for (int i = 0; i < 4; i++) {
            const int idx = tid + i * 256;
            const int r = idx >> 4, q = idx & 15;
            const uint32_t so = (uint32_t)(r * LDA_ + q * 8) * 2;
            const size_t go = (size_t)(j0 + r) * HD_ + q * 8;
            cp16(sk + so,                      kh + go);
            cp16(sk + (uint32_t)KEL * 2 + so,  kl + go);
            cp16(sv + so,                      vhp + go);
            cp16(sv + (uint32_t)KEL * 2 + so,  vlp + go);
        }
        CP_COMMIT();
    };

    const int ntiles = q0 / 64 + 2;
    load_kv(0, 0);

    float m0 = -1e30f, m1 = -1e30f, l0 = 0.f, l1 = 0.f;
    float oa[16][4];
    #pragma unroll
    for (int f = 0; f < 16; f++)
        #pragma unroll
        for (int k = 0; k < 4; k++) oa[f][k] = 0.f;

    const int rg0 = q0 + wid * 16 + g;
    const int rg1 = rg0 + 8;

    for (int t = 0; t < ntiles; t++) {
        const int st = t & 1;
        if (t + 1 < ntiles) { load_kv(t + 1, st ^ 1); cp_wait<1>(); }
        else                { cp_wait<0>(); }
        __syncthreads();

        const uint32_t sk = smb + (uint32_t)(OFF_K0 + st * 2 * KEL) * 2;
        const uint32_t sv = smb + (uint32_t)(OFF_V0 + st * 2 * KEL) * 2;

        float sc[8][4];
        #pragma unroll
        for (int nj = 0; nj < 8; nj++)
            #pragma unroll
            for (int k = 0; k < 4; k++) sc[nj][k] = 0.f;

        #pragma unroll
        for (int kc = 0; kc < 8; kc++) {
            uint32_t ah[4], al[4];
            const uint32_t oq = smb + (uint32_t)((wid * 16 + lrow) * LDA_ + kc * 16 + lcol8) * 2;
            LDSM_X4(ah, oq);
            LDSM_X4(al, oq + (uint32_t)QEL * 2);
            #pragma unroll
            for (int nb = 0; nb < 4; nb++) {
                uint32_t bh4[4], bl4[4];
                const uint32_t ok = sk + (uint32_t)((nb * 16 + lrow) * LDA_ + kc * 16 + lcol8) * 2;
                LDSM_X4(bh4, ok);
                LDSM_X4(bl4, ok + (uint32_t)KEL * 2);
                #pragma unroll
                for (int hf = 0; hf < 2; hf++) {
                    const int nj = nb * 2 + hf;
                    mma_bf16(sc[nj], ah, bh4[hf], bh4[hf + 2]);
                    mma_bf16(sc[nj], ah, bl4[hf], bl4[hf + 2]);
                    mma_bf16(sc[nj], al, bh4[hf], bh4[hf + 2]);
                }
            }
        }

        const int j0 = t * 64;
        if (t >= ntiles - 2) {
            #pragma unroll
            for (int nj = 0; nj < 8; nj++) {
                const int c0 = j0 + nj * 8 + 2 * t4;
                if (c0     > rg0) sc[nj][0] = -1e30f;
                if (c0 + 1 > rg0) sc[nj][1] = -1e30f;
                if (c0     > rg1) sc[nj][2] = -1e30f;
                if (c0 + 1 > rg1) sc[nj][3] = -1e30f;
            }
        }

        float mx0 = -1e30f, mx1 = -1e30f;
        #pragma unroll
        for (int nj = 0; nj < 8; nj++) {
            mx0 = fmaxf(mx0, fmaxf(sc[nj][0], sc[nj][1]));
            mx1 = fmaxf(mx1, fmaxf(sc[nj][2], sc[nj][3]));
        }
        mx0 = fmaxf(mx0, __shfl_xor_sync(0xffffffffu, mx0, 1));
        mx0 = fmaxf(mx0, __shfl_xor_sync(0xffffffffu, mx0, 2));
        mx1 = fmaxf(mx1, __shfl_xor_sync(0xffffffffu, mx1, 1));
        mx1 = fmaxf(mx1, __shfl_xor_sync(0xffffffffu, mx1, 2));
        const float mn0 = fmaxf(m0, mx0), mn1 = fmaxf(m1, mx1);
        const float cr0 = __expf(m0 - mn0), cr1 = __expf(m1 - mn1);
        m0 = mn0; m1 = mn1;
        float rs0 = 0.f, rs1 = 0.f;
        #pragma unroll
        for (int nj = 0; nj < 8; nj++) {
            sc[nj][0] = __expf(sc[nj][0] - mn0);
            sc[nj][1] = __expf(sc[nj][1] - mn0);
            sc[nj][2] = __expf(sc[nj][2] - mn1);
            sc[nj][3] = __expf(sc[nj][3] - mn1);
            rs0 += sc[nj][0] + sc[nj][1];
            rs1 += sc[nj][2] + sc[nj][3];
        }
        rs0 += __shfl_xor_sync(0xffffffffu, rs0, 1);
        rs0 += __shfl_xor_sync(0xffffffffu, rs0, 2);
        rs1 += __shfl_xor_sync(0xffffffffu, rs1, 1);
        rs1 += __shfl_xor_sync(0xffffffffu, rs1, 2);
        l0 = l0 * cr0 + rs0;
        l1 = l1 * cr1 + rs1;
        #pragma unroll
        for (int f = 0; f < 16; f++) {
            oa[f][0] *= cr0; oa[f][1] *= cr0;
            oa[f][2] *= cr1; oa[f][3] *= cr1;
        }

        #pragma unroll
        for (int kc = 0; kc < 4; kc++) {
            uint32_t ph[4], pl[4];
            pack_hilo(sc[2 * kc][0],     sc[2 * kc][1],     ph[0], pl[0]);
            pack_hilo(sc[2 * kc][2],     sc[2 * kc][3],     ph[1], pl[1]);
            pack_hilo(sc[2 * kc + 1][0], sc[2 * kc + 1][1], ph[2], pl[2]);
            pack_hilo(sc[2 * kc + 1][2], sc[2 * kc + 1][3], ph[3], pl[3]);
            #pragma unroll
            for (int dn = 0; dn < 8; dn++) {
                uint32_t vh4[4], vl4[4];
                const uint32_t ov = sv + (uint32_t)((kc * 16 + lrow) * LDA_ + dn * 16 + lcol8) * 2;
                LDSM_X4_T(vh4, ov);
                LDSM_X4_T(vl4, ov + (uint32_t)KEL * 2);
                mma_bf16(oa[2 * dn],     ph, vh4[0], vh4[1]);
                mma_bf16(oa[2 * dn],     ph, vl4[0], vl4[1]);
                mma_bf16(oa[2 * dn],     pl, vh4[0], vh4[1]);
                mma_bf16(oa[2 * dn + 1], ph, vh4[2], vh4[3]);
                mma_bf16(oa[2 * dn + 1], ph, vl4[2], vl4[3]);
                mma_bf16(oa[2 * dn + 1], pl, vh4[2], vh4[3]);
            }
        }
        __syncthreads();
    }

    const float i0 = 1.f / l0, i1 = 1.f / l1;
    const int r0 = q0 + wid * 16 + g;
    #pragma unroll
    for (int f = 0; f < 16; f++) {
        const int col = f * 8 + 2 * t4;
        const size_t o0 = ((size_t)b * S_ + r0) * H_ + h * HD_ + col;
        const size_t o1 = ((size_t)b * S_ + r0 + 8) * H_ + h * HD_ + col;
        *reinterpret_cast<float2*>(g_attn + o0) = make_float2(oa[f][0] * i0, oa[f][1] * i0);
        *reinterpret_cast<float2*>(g_attn + o1) = make_float2(oa[f][2] * i1, oa[f][3] * i1);
    }
}

// ---------------------------------------------------------------------------
extern "C" void kernel_launch(void* const* d_in, const int* in_sizes, int n_in,
                              void* d_out, int out_size)
{
    (void)in_sizes; (void)n_in; (void)out_size;
    const float* hidden = (const float*)d_in[0];
    // d_in[1] = attention_mask: deterministic causal mask, implemented directly.
    const float* w_pack = (const float*)d_in[2];
    const float* w_o    = (const float*)d_in[3];
    float* out = (float*)d_out;

    cudaFuncSetAttribute(gemm_s8<0>, cudaFuncAttributeMaxDynamicSharedMemorySize, GEMM_SMEM);
    cudaFuncSetAttribute(gemm_s8<1>, cudaFuncAttributeMaxDynamicSharedMemorySize, GEMM_SMEM);
    cudaFuncSetAttribute(attn_mma, cudaFuncAttributeMaxDynamicSharedMemorySize, ATTN_SMEM);

    int8_t *h8h, *h8l, *wp8h, *wp8l, *wo8h, *wo8l, *ao8h, *ao8l;
    float *sh, *swp, *swo, *sao, *attn_ptr;
    cudaGetSymbolAddress((void**)&h8h,  g_h8h);  cudaGetSymbolAddress((void**)&h8l,  g_h8l);
    cudaGetSymbolAddress((void**)&wp8h, g_wp8h); cudaGetSymbolAddress((void**)&wp8l, g_wp8l);
    cudaGetSymbolAddress((void**)&wo8h, g_wo8h); cudaGetSymbolAddress((void**)&wo8l, g_wo8l);
    cudaGetSymbolAddress((void**)&ao8h, g_ao8h); cudaGetSymbolAddress((void**)&ao8l, g_ao8l);
    cudaGetSymbolAddress((void**)&sh,  g_sh);  cudaGetSymbolAddress((void**)&swp, g_swp);
    cudaGetSymbolAddress((void**)&swo, g_swo); cudaGetSymbolAddress((void**)&sao, g_sao);
    cudaGetSymbolAddress((void**)&attn_ptr, g_attn);

    const int M = B_ * S_;                       // 4096

    // quantize inputs (per row over K=2048)
    quant_rows<<<M, 256>>>(hidden, h8h, h8l, sh);
    quant_rows<<<3 * H_, 256>>>(w_pack, wp8h, wp8l, swp);
    quant_rows<<<H_, 256>>>(w_o, wo8h, wo8l, swo);

    // K1: QKV projection (int8 3-term) -> q/k/v bf16 hi/lo (q pre-scaled)
    dim3 g1((3 * H_) / 64, M / 128);             // (96, 32)
    gemm_s8<0><<<g1, 256, GEMM_SMEM>>>(h8h, h8l, wp8h, wp8l, sh, swp, nullptr, 3 * H_, H_);

    // K2: causal flash attention (bf16 mma 3-term) -> g_attn fp32
    dim3 g2(S_ / 128, NH_, B_);                  // (16, 16, 2)
    attn_mma<<<g2, 256, ATTN_SMEM>>>();

    // quantize attention output
    quant_rows<<<M, 256>>>(attn_ptr, ao8h, ao8l, sao);

    // K3: output projection (int8 3-term) -> d_out (fp32)
    dim3 g3(H_ / 64, M / 128);                   // (32, 32)
    gemm_s8<1><<<g3, 256, GEMM_SMEM>>>(ao8h, ao8l, wo8h, wo8l, sao, swo, out, H_, H_);
}

// round 14
// speedup vs baseline: 1.0011x; 1.0008x over previous
#include <cuda_runtime.h>
#include <cuda_bf16.h>
#include <math.h>
#include <stdint.h>

#define B_  2
#define S_  2048
#define H_  2048
#define NH_ 16
#define HD_ 128

// int8 quantized operands (h = main, l = residual, x ~= s*(h + l/256))
__device__ int8_t g_h8h[(size_t)B_ * S_ * H_];
__device__ int8_t g_h8l[(size_t)B_ * S_ * H_];
__device__ int8_t g_wp8h[(size_t)3 * H_ * H_];
__device__ int8_t g_wp8l[(size_t)3 * H_ * H_];
__device__ int8_t g_wo8h[(size_t)H_ * H_];
__device__ int8_t g_wo8l[(size_t)H_ * H_];
__device__ int8_t g_ao8h[(size_t)B_ * S_ * H_];
__device__ int8_t g_ao8l[(size_t)B_ * S_ * H_];
__device__ float  g_sh[B_ * S_];
__device__ float  g_swp[3 * H_];
__device__ float  g_swo[H_];
__device__ float  g_sao[B_ * S_];

// bf16 hi/lo q/k/v for attention; fp32 attention output
__device__ __nv_bfloat16 g_q_hi[(size_t)B_ * NH_ * S_ * HD_];
__device__ __nv_bfloat16 g_q_lo[(size_t)B_ * NH_ * S_ * HD_];
__device__ __nv_bfloat16 g_k_hi[(size_t)B_ * NH_ * S_ * HD_];
__device__ __nv_bfloat16 g_k_lo[(size_t)B_ * NH_ * S_ * HD_];
__device__ __nv_bfloat16 g_v_hi[(size_t)B_ * NH_ * S_ * HD_];
__device__ __nv_bfloat16 g_v_lo[(size_t)B_ * NH_ * S_ * HD_];
__device__ float g_attn[(size_t)B_ * S_ * H_];

// ---------------------------------------------------------------------------
// helpers
// ---------------------------------------------------------------------------
__device__ __forceinline__ uint32_t smem_u32(const void* p) {
    uint32_t a;
    asm("{ .reg .u64 t; cvta.to.shared.u64 t, %1; cvt.u32.u64 %0, t; }" : "=r"(a) : "l"(p));
    return a;
}
#define LDSM_X4(r, addr) \
    asm volatile("ldmatrix.sync.aligned.m8n8.x4.shared.b16 {%0,%1,%2,%3}, [%4];" \
        : "=r"((r)[0]), "=r"((r)[1]), "=r"((r)[2]), "=r"((r)[3]) : "r"(addr))
#define LDSM_X4_T(r, addr) \
    asm volatile("ldmatrix.sync.aligned.m8n8.x4.trans.shared.b16 {%0,%1,%2,%3}, [%4];" \
        : "=r"((r)[0]), "=r"((r)[1]), "=r"((r)[2]), "=r"((r)[3]) : "r"(addr))

__device__ __forceinline__ void mma_bf16(float* c, const uint32_t* a, uint32_t b0, uint32_t b1) {
    asm volatile("mma.sync.aligned.m16n8k16.row.col.f32.bf16.bf16.f32 "
                 "{%0,%1,%2,%3}, {%4,%5,%6,%7}, {%8,%9}, {%0,%1,%2,%3};"
                 : "+f"(c[0]), "+f"(c[1]), "+f"(c[2]), "+f"(c[3])
                 : "r"(a[0]), "r"(a[1]), "r"(a[2]), "r"(a[3]), "r"(b0), "r"(b1));
}
__device__ __forceinline__ void mma_s8(int* c, const uint32_t* a, uint32_t b0, uint32_t b1) {
    asm volatile("mma.sync.aligned.m16n8k32.row.col.s32.s8.s8.s32 "
                 "{%0,%1,%2,%3}, {%4,%5,%6,%7}, {%8,%9}, {%0,%1,%2,%3};"
                 : "+r"(c[0]), "+r"(c[1]), "+r"(c[2]), "+r"(c[3])
                 : "r"(a[0]), "r"(a[1]), "r"(a[2]), "r"(a[3]), "r"(b0), "r"(b1));
}
__device__ __forceinline__ void cp16(uint32_t dst, const void* src) {
    asm volatile("cp.async.cg.shared.global [%0], [%1], 16;" :: "r"(dst), "l"(src) : "memory");
}
#define CP_COMMIT() asm volatile("cp.async.commit_group;" ::: "memory")
template <int N> __device__ __forceinline__ void cp_wait() {
    asm volatile("cp.async.wait_group %0;" :: "n"(N) : "memory");
}
__device__ __forceinline__ void pack_hilo(float x, float y, uint32_t& hi, uint32_t& lo) {
    __nv_bfloat162 h = __float22bfloat162_rn(make_float2(x, y));
    __nv_bfloat162 l = __float22bfloat162_rn(make_float2(x - __bfloat162float(h.x),
                                                         y - __bfloat162float(h.y)));
    hi = *reinterpret_cast<uint32_t*>(&h);
    lo = *reinterpret_cast<uint32_t*>(&l);
}
__device__ __forceinline__ int clamp127(int v) { return max(-127, min(127, v)); }
__device__ __forceinline__ uint32_t pk4(int a, int b, int c, int d) {
    return (uint32_t)(a & 255) | ((uint32_t)(b & 255) << 8) |
           ((uint32_t)(c & 255) << 16) | ((uint32_t)(d & 255) << 24);
}

// ---------------------------------------------------------------------------
// row quantization: fp32 row (K=2048) -> int8 h + int8 l + scale
// ---------------------------------------------------------------------------
__global__ __launch_bounds__(256)
void quant_rows(const float* __restrict__ src, int8_t* __restrict__ h8,
                int8_t* __restrict__ l8, float* __restrict__ scale)
{
    const int row = blockIdx.x;
    const float* p = src + (size_t)row * 2048;
    const int t = threadIdx.x, lane = t & 31, w = t >> 5;
    float x[8];
    *reinterpret_cast<float4*>(x)     = *reinterpret_cast<const float4*>(p + t * 8);
    *reinterpret_cast<float4*>(x + 4) = *reinterpret_cast<const float4*>(p + t * 8 + 4);
    float mx = 0.f;
    #pragma unroll
    for (int j = 0; j < 8; j++) mx = fmaxf(mx, fabsf(x[j]));
    #pragma unroll
    for (int off = 16; off; off >>= 1) mx = fmaxf(mx, __shfl_xor_sync(0xffffffffu, mx, off));
    __shared__ float wm[8];
    if (lane == 0) wm[w] = mx;
    __syncthreads();
    mx = wm[0];
    #pragma unroll
    for (int j = 1; j < 8; j++) mx = fmaxf(mx, wm[j]);

    const float s = mx * (1.f / 127.f);
    const float inv = (mx > 0.f) ? 127.f / mx : 0.f;
    const float inv2 = inv * 256.f;
    int h[8], l[8];
    #pragma unroll
    for (int j = 0; j < 8; j++) {
        h[j] = clamp127(__float2int_rn(x[j] * inv));
        const float r = x[j] - (float)h[j] * s;
        l[j] = clamp127(__float2int_rn(r * inv2));
    }
    *reinterpret_cast<uint2*>(h8 + (size_t)row * 2048 + t * 8) =
        make_uint2(pk4(h[0], h[1], h[2], h[3]), pk4(h[4], h[5], h[6], h[7]));
    *reinterpret_cast<uint2*>(l8 + (size_t)row * 2048 + t * 8) =
        make_uint2(pk4(l[0], l[1], l[2], l[3]), pk4(l[4], l[5], l[6], l[7]));
    if (t == 0) scale[row] = s;
}

// ---------------------------------------------------------------------------
// int8 3-term GEMM: C = A @ B^T, A,B int8 h/l + per-row scales.
// CTA 128x64, BK=64 int8, 256 threads, 2 CTA/SM, cp.async double buffer.
// EPI==0: emit q(scaled)/k/v bf16 hi/lo. EPI==1: fp32 store to C.
// ---------------------------------------------------------------------------
constexpr int AEL8 = 128 * 80;                  // bytes per A component
constexpr int BEL8 = 64 * 80;
constexpr int STG8 = 2 * AEL8 + 2 * BEL8;       // 30720
constexpr int GEMM_SMEM = 2 * STG8;             // 61440

template <int EPI>
__global__ __launch_bounds__(256, 2)
void gemm_s8(const int8_t* __restrict__ Ah, const int8_t* __restrict__ Al,
             const int8_t* __restrict__ Bh, const int8_t* __restrict__ Bl,
             const float* __restrict__ sa, const float* __restrict__ sb,
             float* __restrict__ C, int N, int K)
{
    extern __shared__ int8_t sm8[];
    const int bm = blockIdx.y * 128, bn = blockIdx.x * 64;
    const int tid = threadIdx.x, wid = tid >> 5, lane = tid & 31;
    const int wm = wid >> 1, wn = wid & 1;
    const int lrow = lane & 15;
    const int koff16 = (lane >> 4) * 16;
    const uint32_t smb = smem_u32(sm8);

    const int8_t* gA[2] = { Ah + (size_t)bm * K, Al + (size_t)bm * K };
    const int8_t* gB[2] = { Bh + (size_t)bn * K, Bl + (size_t)bn * K };

    auto load_stage = [&](int k0, int s) {
        const uint32_t sbb = smb + (uint32_t)(s * STG8);
        #pragma unroll
        for (int c = 0; c < 2; c++)
            #pragma unroll
            for (int i = 0; i < 2; i++) {
                const int idx = tid + i * 256;
                const int r = idx >> 2, q = idx & 3;
                cp16(sbb + (uint32_t)(c * AEL8 + r * 80 + q * 16),
                     gA[c] + (size_t)r * K + k0 + q * 16);
            }
        #pragma unroll
        for (int c = 0; c < 2; c++) {
            const int r = tid >> 2, q = tid & 3;
            cp16(sbb + (uint32_t)(2 * AEL8 + c * BEL8 + r * 80 + q * 16),
                 gB[c] + (size_t)r * K + k0 + q * 16);
        }
        CP_COMMIT();
    };

    int acc_h[2][4][4], acc_x[2][4][4];
    #pragma unroll
    for (int i = 0; i < 2; i++)
        #pragma unroll
        for (int j = 0; j < 4; j++)
            #pragma unroll
            for (int k = 0; k < 4; k++) { acc_h[i][j][k] = 0; acc_x[i][j][k] = 0; }

    const int niter = K >> 6;      // BK = 64
    load_stage(0, 0);

    for (int it = 0; it < niter; it++) {
        const int s = it & 1;
        if (it + 1 < niter) { load_stage((it + 1) << 6, s ^ 1); cp_wait<1>(); }
        else                { cp_wait<0>(); }
        __syncthreads();

        const uint32_t sbb = smb + (uint32_t)(s * STG8);
        #pragma unroll
        for (int kk = 0; kk < 2; kk++) {
            const uint32_t kb = (uint32_t)(kk * 32 + koff16);
            uint32_t bh4[2][4], bl4[2][4];
            #pragma unroll
            for (int nb = 0; nb < 2; nb++) {
                const uint32_t ok = sbb + (uint32_t)(2 * AEL8 + (wn * 32 + nb * 16 + lrow) * 80) + kb;
                LDSM_X4(bh4[nb], ok);
                LDSM_X4(bl4[nb], ok + (uint32_t)BEL8);
            }
            #pragma unroll
            for (int mi = 0; mi < 2; mi++) {
                uint32_t ah[4], al[4];
                const uint32_t oa = sbb + (uint32_t)((wm * 32 + mi * 16 + lrow) * 80) + kb;
                LDSM_X4(ah, oa);
                LDSM_X4(al, oa + (uint32_t)AEL8);
                #pragma unroll
                for (int nb = 0; nb < 2; nb++)
                    #pragma unroll
                    for (int hf = 0; hf < 2; hf++) {
                        const int nj = nb * 2 + hf;
                        mma_s8(acc_h[mi][nj], ah, bh4[nb][hf], bh4[nb][hf + 2]);
                        mma_s8(acc_x[mi][nj], ah, bl4[nb][hf], bl4[nb][hf + 2]);
                        mma_s8(acc_x[mi][nj], al, bh4[nb][hf], bh4[nb][hf + 2]);
                    }
            }
        }
        __syncthreads();
    }

    // epilogue: dequant C = sa[m]*sb[n]*(hh + cross/256)
    const int g = lane >> 2, t4 = lane & 3;
    #pragma unroll
    for (int mi = 0; mi < 2; mi++) {
        const int m0 = bm + wm * 32 + mi * 16 + g;
        const int m1 = m0 + 8;
        const float sa0 = sa[m0], sa1 = sa[m1];
        #pragma unroll
        for (int nj = 0; nj < 4; nj++) {
            const int col = wn * 32 + nj * 8 + 2 * t4;
            const float2 sbv = *reinterpret_cast<const float2*>(sb + bn + col);
            float f[4];
            f[0] = ((float)acc_h[mi][nj][0] + (float)acc_x[mi][nj][0] * 0.00390625f) * sa0 * sbv.x;
            f[1] = ((float)acc_h[mi][nj][1] + (float)acc_x[mi][nj][1] * 0.00390625f) * sa0 * sbv.y;
            f[2] = ((float)acc_h[mi][nj][2] + (float)acc_x[mi][nj][2] * 0.00390625f) * sa1 * sbv.x;
            f[3] = ((float)acc_h[mi][nj][3] + (float)acc_x[mi][nj][3] * 0.00390625f) * sa1 * sbv.y;
            if (EPI == 0) {
                const int gcol = bn + col;
                const int three = gcol >> 11;
                const int nh    = (gcol & 2047) >> 7;
                const int hd    = gcol & 127;
                __nv_bfloat16 *dh, *dl;
                if (three == 0)      { dh = g_q_hi; dl = g_q_lo; }
                else if (three == 1) { dh = g_k_hi; dl = g_k_lo; }
                else                 { dh = g_v_hi; dl = g_v_lo; }
                const float scl = (three == 0) ? 0.08838834764831845f : 1.0f;
                #pragma unroll
                for (int half = 0; half < 2; half++) {
                    const int m = (half == 0) ? m0 : m1;
                    const int bi = m >> 11, si = m & 2047;
                    const size_t o = (((size_t)bi * NH_ + nh) * S_ + si) * HD_ + hd;
                    uint32_t hv, lv;
                    pack_hilo(f[half * 2] * scl, f[half * 2 + 1] * scl, hv, lv);
                    *reinterpret_cast<uint32_t*>(dh + o) = hv;
                    *reinterpret_cast<uint32_t*>(dl + o) = lv;
                }
            } else {
                *reinterpret_cast<float2*>(C + (size_t)m0 * N + bn + col) = make_float2(f[0], f[1]);
                *reinterpret_cast<float2*>(C + (size_t)m1 * N + bn + col) = make_float2(f[2], f[3]);
            }
        }
    }
}

// ---------------------------------------------------------------------------
// Causal flash attention via bf16 mma.sync 3-term. BQ=128, BC=64, 256 threads.
// Output: fp32 g_attn [b, s, H].
// ---------------------------------------------------------------------------
constexpr int LDA_ = 136;
constexpr int QEL = 128 * LDA_;
constexpr int KEL = 64 * LDA_;
constexpr int OFF_K0 = 2 * QEL;
constexpr int OFF_V0 = 2 * QEL + 4 * KEL;
constexpr int ATTN_SMEM = (2 * QEL + 8 * KEL) * 2;   // 208896 B

__global__ __launch_bounds__(256)
void attn_mma()
{
    extern __shared__ __nv_bfloat16 sm[];
    const int q0 = blockIdx.x * 128;
    const int h = blockIdx.y, b = blockIdx.z;
    const int tid = threadIdx.x, wid = tid >> 5, lane = tid & 31;
    const int g = lane >> 2, t4 = lane & 3;
    const int lrow = lane & 15, lcol8 = (lane >> 4) * 8;
    const uint32_t smb = smem_u32(sm);

    const size_t hoff = ((size_t)b * NH_ + h) * S_ * HD_;
    const __nv_bfloat16* qh = g_q_hi + hoff + (size_t)q0 * HD_;
    const __nv_bfloat16* ql = g_q_lo + hoff + (size_t)q0 * HD_;
    const __nv_bfloat16* kh = g_k_hi + hoff;
    const __nv_bfloat16* kl = g_k_lo + hoff;
    const __nv_bfloat16* vhp = g_v_hi + hoff;
    const __nv_bfloat16* vlp = g_v_lo + hoff;

    #pragma unroll
    for (int i = 0; i < 8; i++) {
        const int idx = tid + i * 256;
        const int r = idx >> 4, q = idx & 15;
        *reinterpret_cast<uint4*>(sm + r * LDA_ + q * 8) =
            *reinterpret_cast<const uint4*>(qh + (size_t)r * HD_ + q * 8);
        *reinterpret_cast<uint4*>(sm + QEL + r * LDA_ + q * 8) =
            *reinterpret_cast<const uint4*>(ql + (size_t)r * HD_ + q * 8);
    }

    auto load_kv = [&](int t, int s) {
        const int j0 = t * 64;
        const uint32_t sk = smb + (uint32_t)(OFF_K0 + s * 2 * KEL) * 2;
        const uint32_t sv = smb + (uint32_t)(OFF_V0 + s * 2 * KEL) * 2;
        #pragma unroll
        for (int i = 0; i < 4; i++) {
            const int idx = tid + i * 256;
            const int r = idx >> 4, q = idx & 15;
            const uint32_t so = (uint32_t)(r * LDA_ + q * 8) * 2;
            const size_t go = (size_t)(j0 + r) * HD_ + q * 8;
            cp16(sk + so,                      kh + go);
            cp16(sk + (uint32_t)KEL * 2 + so,  kl + go);
            cp16(sv + so,                      vhp + go);
            cp16(sv + (uint32_t)KEL * 2 + so,  vlp + go);
        }
        CP_COMMIT();
    };

    const int ntiles = q0 / 64 + 2;
    load_kv(0, 0);

    float m0 = -1e30f, m1 = -1e30f, l0 = 0.f, l1 = 0.f;
    float oa[16][4];
    #pragma unroll
    for (int f = 0; f < 16; f++)
        #pragma unroll
        for (int k = 0; k < 4; k++) oa[f][k] = 0.f;

    const int rg0 = q0 + wid * 16 + g;
    const int rg1 = rg0 + 8;

    for (int t = 0; t < ntiles; t++) {
        const int st = t & 1;
        if (t + 1 < ntiles) { load_kv(t + 1, st ^ 1); cp_wait<1>(); }
        else                { cp_wait<0>(); }
        __syncthreads();

        const uint32_t sk = smb + (uint32_t)(OFF_K0 + st * 2 * KEL) * 2;
        const uint32_t sv = smb + (uint32_t)(OFF_V0 + st * 2 * KEL) * 2;

        float sc[8][4];
        #pragma unroll
        for (int nj = 0; nj < 8; nj++)
            #pragma unroll
            for (int k = 0; k < 4; k++) sc[nj][k] = 0.f;

        #pragma unroll
        for (int kc = 0; kc < 8; kc++) {
            uint32_t ah[4], al[4];
            const uint32_t oq = smb + (uint32_t)((wid * 16 + lrow) * LDA_ + kc * 16 + lcol8) * 2;
            LDSM_X4(ah, oq);
            LDSM_X4(al, oq + (uint32_t)QEL * 2);
            #pragma unroll
            for (int nb = 0; nb < 4; nb++) {
                uint32_t bh4[4], bl4[4];
                const uint32_t ok = sk + (uint32_t)((nb * 16 + lrow) * LDA_ + kc * 16 + lcol8) * 2;
                LDSM_X4(bh4, ok);
                LDSM_X4(bl4, ok + (uint32_t)KEL * 2);
                #pragma unroll
                for (int hf = 0; hf < 2; hf++) {
                    const int nj = nb * 2 + hf;
                    mma_bf16(sc[nj], ah, bh4[hf], bh4[hf + 2]);
                    mma_bf16(sc[nj], ah, bl4[hf], bl4[hf + 2]);
                    mma_bf16(sc[nj], al, bh4[hf], bh4[hf + 2]);
                }
            }
        }

        const int j0 = t * 64;
        if (t >= ntiles - 2) {
            #pragma unroll
            for (int nj = 0; nj < 8; nj++) {
                const int c0 = j0 + nj * 8 + 2 * t4;
                if (c0     > rg0) sc[nj][0] = -1e30f;
                if (c0 + 1 > rg0) sc[nj][1] = -1e30f;
                if (c0     > rg1) sc[nj][2] = -1e30f;
                if (c0 + 1 > rg1) sc[nj][3] = -1e30f;
            }
        }

        float mx0 = -1e30f, mx1 = -1e30f;
        #pragma unroll
        for (int nj = 0; nj < 8; nj++) {
            mx0 = fmaxf(mx0, fmaxf(sc[nj][0], sc[nj][1]));
            mx1 = fmaxf(mx1, fmaxf(sc[nj][2], sc[nj][3]));
        }
        mx0 = fmaxf(mx0, __shfl_xor_sync(0xffffffffu, mx0, 1));
        mx0 = fmaxf(mx0, __shfl_xor_sync(0xffffffffu, mx0, 2));
        mx1 = fmaxf(mx1, __shfl_xor_sync(0xffffffffu, mx1, 1));
        mx1 = fmaxf(mx1, __shfl_xor_sync(0xffffffffu, mx1, 2));
        const float mn0 = fmaxf(m0, mx0), mn1 = fmaxf(m1, mx1);
        const float cr0 = __expf(m0 - mn0), cr1 = __expf(m1 - mn1);
        m0 = mn0; m1 = mn1;
        float rs0 = 0.f, rs1 = 0.f;
        #pragma unroll
        for (int nj = 0; nj < 8; nj++) {
            sc[nj][0] = __expf(sc[nj][0] - mn0);
            sc[nj][1] = __expf(sc[nj][1] - mn0);
            sc[nj][2] = __expf(sc[nj][2] - mn1);
            sc[nj][3] = __expf(sc[nj][3] - mn1);
            rs0 += sc[nj][0] + sc[nj][1];
            rs1 += sc[nj][2] + sc[nj][3];
        }
        rs0 += __shfl_xor_sync(0xffffffffu, rs0, 1);
        rs0 += __shfl_xor_sync(0xffffffffu, rs0, 2);
        rs1 += __shfl_xor_sync(0xffffffffu, rs1, 1);
        rs1 += __shfl_xor_sync(0xffffffffu, rs1, 2);
        l0 = l0 * cr0 + rs0;
        l1 = l1 * cr1 + rs1;
        #pragma unroll
        for (int f = 0; f < 16; f++) {
            oa[f][0] *= cr0; oa[f][1] *= cr0;
            oa[f][2] *= cr1; oa[f][3] *= cr1;
        }

        #pragma unroll
        for (int kc = 0; kc < 4; kc++) {
            uint32_t ph[4], pl[4];
            pack_hilo(sc[2 * kc][0],     sc[2 * kc][1],     ph[0], pl[0]);
            pack_hilo(sc[2 * kc][2],     sc[2 * kc][3],     ph[1], pl[1]);
            pack_hilo(sc[2 * kc + 1][0], sc[2 * kc + 1][1], ph[2], pl[2]);
            pack_hilo(sc[2 * kc + 1][2], sc[2 * kc + 1][3], ph[3], pl[3]);
            #pragma unroll
            for (int dn = 0; dn < 8; dn++) {
                uint32_t vh4[4], vl4[4];
                const uint32_t ov = sv + (uint32_t)((kc * 16 + lrow) * LDA_ + dn * 16 + lcol8) * 2;
                LDSM_X4_T(vh4, ov);
                LDSM_X4_T(vl4, ov + (uint32_t)KEL * 2);
                mma_bf16(oa[2 * dn],     ph, vh4[0], vh4[1]);
                mma_bf16(oa[2 * dn],     ph, vl4[0], vl4[1]);
                mma_bf16(oa[2 * dn],     pl, vh4[0], vh4[1]);
                mma_bf16(oa[2 * dn + 1], ph, vh4[2], vh4[3]);
                mma_bf16(oa[2 * dn + 1], ph, vl4[2], vl4[3]);
                mma_bf16(oa[2 * dn + 1], pl, vh4[2], vh4[3]);
            }
        }
        __syncthreads();
    }

    const float i0 = 1.f / l0, i1 = 1.f / l1;
    const int r0 = q0 + wid * 16 + g;
    #pragma unroll
    for (int f = 0; f < 16; f++) {
        const int col = f * 8 + 2 * t4;
        const size_t o0 = ((size_t)b * S_ + r0) * H_ + h * HD_ + col;
        const size_t o1 = ((size_t)b * S_ + r0 + 8) * H_ + h * HD_ + col;
        *reinterpret_cast<float2*>(g_attn + o0) = make_float2(oa[f][0] * i0, oa[f][1] * i0);
        *reinterpret_cast<float2*>(g_attn + o1) = make_float2(oa[f][2] * i1, oa[f][3] * i1);
    }
}

// ---------------------------------------------------------------------------
extern "C" void kernel_launch(void* const* d_in, const int* in_sizes, int n_in,
                              void* d_out, int out_size)
{
    (void)in_sizes; (void)n_in; (void)out_size;
    const float* hidden = (const float*)d_in[0];
    // d_in[1] = attention_mask: deterministic causal mask, implemented directly.
    const float* w_pack = (const float*)d_in[2];
    const float* w_o    = (const float*)d_in[3];
    float* out = (float*)d_out;

    cudaFuncSetAttribute(gemm_s8<0>, cudaFuncAttributeMaxDynamicSharedMemorySize, GEMM_SMEM);
    cudaFuncSetAttribute(gemm_s8<1>, cudaFuncAttributeMaxDynamicSharedMemorySize, GEMM_SMEM);
    cudaFuncSetAttribute(attn_mma, cudaFuncAttributeMaxDynamicSharedMemorySize, ATTN_SMEM);

    int8_t *h8h, *h8l, *wp8h, *wp8l, *wo8h, *wo8l, *ao8h, *ao8l;
    float *sh, *swp, *swo, *sao, *attn_ptr;
    cudaGetSymbolAddress((void**)&h8h,  g_h8h);  cudaGetSymbolAddress((void**)&h8l,  g_h8l);
    cudaGetSymbolAddress((void**)&wp8h, g_wp8h); cudaGetSymbolAddress((void**)&wp8l, g_wp8l);
    cudaGetSymbolAddress((void**)&wo8h, g_wo8h); cudaGetSymbolAddress((void**)&wo8l, g_wo8l);
    cudaGetSymbolAddress((void**)&ao8h, g_ao8h); cudaGetSymbolAddress((void**)&ao8l, g_ao8l);
    cudaGetSymbolAddress((void**)&sh,  g_sh);  cudaGetSymbolAddress((void**)&swp, g_swp);
    cudaGetSymbolAddress((void**)&swo, g_swo); cudaGetSymbolAddress((void**)&sao, g_sao);
    cudaGetSymbolAddress((void**)&attn_ptr, g_attn);

    const int M = B_ * S_;                       // 4096

    // quantize inputs (per row over K=2048)
    quant_rows<<<M, 256>>>(hidden, h8h, h8l, sh);
    quant_rows<<<3 * H_, 256>>>(w_pack, wp8h, wp8l, swp);
    quant_rows<<<H_, 256>>>(w_o, wo8h, wo8l, swo);

    // K1: QKV projection (int8 3-term) -> q/k/v bf16 hi/lo (q pre-scaled)
    dim3 g1((3 * H_) / 64, M / 128);             // (96, 32)
    gemm_s8<0><<<g1, 256, GEMM_SMEM>>>(h8h, h8l, wp8h, wp8l, sh, swp, nullptr, 3 * H_, H_);

    // K2: causal flash attention (bf16 mma 3-term) -> g_attn fp32
    dim3 g2(S_ / 128, NH_, B_);                  // (16, 16, 2)
    attn_mma<<<g2, 256, ATTN_SMEM>>>();

    // quantize attention output
    quant_rows<<<M, 256>>>(attn_ptr, ao8h, ao8l, sao);

    // K3: output projection (int8 3-term) -> d_out (fp32)
    dim3 g3(H_ / 64, M / 128);                   // (32, 32)
    gemm_s8<1><<<g3, 256, GEMM_SMEM>>>(ao8h, ao8l, wo8h, wo8l, sao, swo, out, H_, H_);
}